// round 12
// baseline (speedup 1.0000x reference)
#include <cuda_runtime.h>

// y = min(((x + 1) * 0.75)^2, 10)  — elementwise over 8192*8192 fp32.
// Proven-best structure (R5/R9-R11: wall 82.0-82.2us, ncu 73.7-74.6us,
// DRAM 81.5-82.5%) + ONE de-confounded change: store-streaming (__stcs)
// only. R3 confounded ldcs+stcs with a structure change; this isolates
// whether evict-first output lines free L2 sectors for the read stream.
//
//  - 4 independent front-batched float4 loads per thread (MLP_p1=4)
//  - default-policy loads, __stcs streaming stores
//  - coalesced blockDim-stride addressing, 512-thread blocks
//  - exact grid: 67108864 = 8192 blocks * 512 thr * 16 elems

#define T 512u

__device__ __forceinline__ float f(float x) {
    float t = (x + 1.0f) * 0.75f;
    float y = t * t;
    return fminf(y, 10.0f);
}

__device__ __forceinline__ float4 f4(float4 v) {
    float4 r;
    r.x = f(v.x); r.y = f(v.y); r.z = f(v.z); r.w = f(v.w);
    return r;
}

__global__ __launch_bounds__(512) void elemwise_kernel(const float4* __restrict__ in,
                                                       float4* __restrict__ out) {
    unsigned base = blockIdx.x * (T * 4u) + threadIdx.x;

    // Front-batch 4 independent loads (default cache policy) -> MLP=4.
    float4 v0 = in[base + 0u * T];
    float4 v1 = in[base + 1u * T];
    float4 v2 = in[base + 2u * T];
    float4 v3 = in[base + 3u * T];

    // Streaming stores: output has zero reuse; evict-first keeps L2
    // sectors available for the inbound read stream.
    __stcs(&out[base + 0u * T], f4(v0));
    __stcs(&out[base + 1u * T], f4(v1));
    __stcs(&out[base + 2u * T], f4(v2));
    __stcs(&out[base + 3u * T], f4(v3));
}

extern "C" void kernel_launch(void* const* d_in, const int* in_sizes, int n_in,
                              void* d_out, int out_size) {
    const float4* in = (const float4*)d_in[0];
    float4* out = (float4*)d_out;
    int n = in_sizes[0];            // 67108864
    int n4 = n / 4;                 // 16777216 float4s
    int blocks = n4 / (512 * 4);    // 8192, exact
    elemwise_kernel<<<blocks, 512>>>(in, out);
}